// round 2
// baseline (speedup 1.0000x reference)
#include <cuda_runtime.h>
#include <cstdint>

// ---------------- device scratch (no allocations allowed) ----------------
#define N_NODES 50000
#define D_FEAT  128

__device__ float g_neigh[(size_t)N_NODES * D_FEAT];   // 25.6 MB accumulator
__device__ float g_deg[N_NODES];                      // weighted degree
__device__ float g_stats[256];                        // [0:128) colsum, [128:256) colsumsq
__device__ float g_scale[128];
__device__ float g_shift[128];
__device__ float g_wt[256 * 128];                     // transposed + swizzled combined W

// swizzle function: chunk permutation per k-row so both GEMM reads and
// the prep layout are conflict-free
__device__ __forceinline__ int swz(int k) {
    return ((k >> 2) & 31) ^ ((k & 3) << 3);
}

// ---------------- kernel 1: zero accumulators ----------------
__global__ void k_zero(int nn4, int nd4) {
    int i = blockIdx.x * blockDim.x + threadIdx.x;
    float4 z = {0.f, 0.f, 0.f, 0.f};
    if (i < nn4) ((float4*)g_neigh)[i] = z;
    if (i < nd4) ((float4*)g_deg)[i] = z;
    if (i < 64)  ((float4*)g_stats)[i] = z;
}

// ---------------- kernel 2: prep combined transposed W ----------------
// Logical combined weight Wc[k][o]: k<128 -> W_self[o][k]; k>=128 -> W_neigh[o][k-128]
// Stored as [k][phys_chunk][4] where phys_chunk = logical_chunk ^ swz(k)
__global__ void k_wprep(const float* __restrict__ Wneigh,
                        const float* __restrict__ Wself) {
    int t = blockIdx.x * 256 + threadIdx.x;   // 0..8191
    if (t >= 256 * 32) return;
    int k = t >> 5;
    int phys = t & 31;
    int o4 = phys ^ swz(k);                   // logical chunk stored at phys
    const float* W = (k < 128) ? Wself : Wneigh;
    int kk = k & 127;
    float4 v;
    v.x = W[(o4 * 4 + 0) * 128 + kk];
    v.y = W[(o4 * 4 + 1) * 128 + kk];
    v.z = W[(o4 * 4 + 2) * 128 + kk];
    v.w = W[(o4 * 4 + 3) * 128 + kk];
    ((float4*)g_wt)[t] = v;
}

// ---------------- kernel 3: edge scatter (one warp per edge) ----------------
__global__ void k_scatter(const float* __restrict__ feat,
                          const int* __restrict__ src,
                          const int* __restrict__ dst,
                          const float* __restrict__ ew,
                          int E) {
    int e = blockIdx.x * 8 + (threadIdx.x >> 5);
    if (e >= E) return;
    int lane = threadIdx.x & 31;
    int s = __ldg(src + e);
    int d = __ldg(dst + e);
    float w = __ldg(ew + e);
    float4 v = __ldg((const float4*)feat + (size_t)s * 32 + lane);
    v.x *= w; v.y *= w; v.z *= w; v.w *= w;
    float4* outp = (float4*)g_neigh + (size_t)d * 32 + lane;
    asm volatile("red.global.add.v4.f32 [%0], {%1,%2,%3,%4};"
                 :: "l"(outp), "f"(v.x), "f"(v.y), "f"(v.z), "f"(v.w)
                 : "memory");
    if (lane == 0) atomicAdd(g_deg + d, w);
}

// ---------------- kernel 4: fused GEMM + bias + relu + BN-stats ----------------
// Block: 256 threads, 64 nodes. K = 256 (feat 0..127, normalized neigh 128..255).
// smem: Ws [256][32 float4 chunks] (128 KB) + Xs [64][256] floats (64 KB)
__global__ void __launch_bounds__(256, 1)
k_gemm(const float* __restrict__ feat,
       const float* __restrict__ b_self,
       const float* __restrict__ bias,
       float* __restrict__ out,
       int N) {
    extern __shared__ float sm[];
    float* Wsm = sm;            // 32768 floats
    float* Xsm = sm + 32768;    // 16384 floats
    int tid = threadIdx.x;

    // stage W (linear, conflict-free, layout already final)
    {
        const float4* wg = (const float4*)g_wt;
        float4* ws4 = (float4*)Wsm;
#pragma unroll
        for (int i = 0; i < 32; ++i) ws4[tid + i * 256] = wg[tid + i * 256];
    }

    // stage X tile: Xs[n][k], natural layout (reads are warp-uniform broadcasts)
    int n0 = blockIdx.x * 64;
    {
        float4* xs4 = (float4*)Xsm;
        const float4* f4 = (const float4*)feat;
        const float4* g4 = (const float4*)g_neigh;
#pragma unroll
        for (int it = 0; it < 16; ++it) {
            int idx = tid + it * 256;
            int n  = idx >> 6;
            int ch = idx & 63;
            int gn = n0 + n;
            float4 v = {0.f, 0.f, 0.f, 0.f};
            if (gn < N) {
                if (ch < 32) {
                    v = f4[(size_t)gn * 32 + ch];
                } else {
                    float inv = 1.0f / (g_deg[gn] + 1e-8f);
                    v = g4[(size_t)gn * 32 + (ch - 32)];
                    v.x *= inv; v.y *= inv; v.z *= inv; v.w *= inv;
                }
            }
            xs4[n * 64 + ch] = v;
        }
    }
    __syncthreads();

    int ox = tid & 31;    // output chunk: cols ox*4 .. ox*4+3
    int ny = tid >> 5;    // node group: nodes ny*8 .. ny*8+7

    float4 acc[8];
#pragma unroll
    for (int j = 0; j < 8; ++j) acc[j] = make_float4(0.f, 0.f, 0.f, 0.f);

    const float4* wr = (const float4*)Wsm;
    const float4* xr = (const float4*)Xsm + (size_t)(ny * 8) * 64;

#pragma unroll 4
    for (int k4 = 0; k4 < 64; ++k4) {
        int b = ox ^ (k4 & 31);
        float4 w0 = wr[(k4 * 4 + 0) * 32 + b];
        float4 w1 = wr[(k4 * 4 + 1) * 32 + (b ^ 8)];
        float4 w2 = wr[(k4 * 4 + 2) * 32 + (b ^ 16)];
        float4 w3 = wr[(k4 * 4 + 3) * 32 + (b ^ 24)];
#pragma unroll
        for (int j = 0; j < 8; ++j) {
            float4 x = xr[j * 64 + k4];
            acc[j].x = fmaf(x.x, w0.x, acc[j].x);
            acc[j].y = fmaf(x.x, w0.y, acc[j].y);
            acc[j].z = fmaf(x.x, w0.z, acc[j].z);
            acc[j].w = fmaf(x.x, w0.w, acc[j].w);
            acc[j].x = fmaf(x.y, w1.x, acc[j].x);
            acc[j].y = fmaf(x.y, w1.y, acc[j].y);
            acc[j].z = fmaf(x.y, w1.z, acc[j].z);
            acc[j].w = fmaf(x.y, w1.w, acc[j].w);
            acc[j].x = fmaf(x.z, w2.x, acc[j].x);
            acc[j].y = fmaf(x.z, w2.y, acc[j].y);
            acc[j].z = fmaf(x.z, w2.z, acc[j].z);
            acc[j].w = fmaf(x.z, w2.w, acc[j].w);
            acc[j].x = fmaf(x.w, w3.x, acc[j].x);
            acc[j].y = fmaf(x.w, w3.y, acc[j].y);
            acc[j].z = fmaf(x.w, w3.z, acc[j].z);
            acc[j].w = fmaf(x.w, w3.w, acc[j].w);
        }
    }

    // epilogue: + (b_self + bias), relu, store, local BN stats
    float4 bb;
    {
        float4 b1 = __ldg((const float4*)b_self + ox);
        float4 b2 = __ldg((const float4*)bias + ox);
        bb.x = b1.x + b2.x; bb.y = b1.y + b2.y;
        bb.z = b1.z + b2.z; bb.w = b1.w + b2.w;
    }
    float4 ls  = {0.f, 0.f, 0.f, 0.f};
    float4 lss = {0.f, 0.f, 0.f, 0.f};
#pragma unroll
    for (int j = 0; j < 8; ++j) {
        int gn = n0 + ny * 8 + j;
        if (gn < N) {
            float4 v;
            v.x = fmaxf(acc[j].x + bb.x, 0.f);
            v.y = fmaxf(acc[j].y + bb.y, 0.f);
            v.z = fmaxf(acc[j].z + bb.z, 0.f);
            v.w = fmaxf(acc[j].w + bb.w, 0.f);
            ((float4*)out)[(size_t)gn * 32 + ox] = v;
            ls.x += v.x; ls.y += v.y; ls.z += v.z; ls.w += v.w;
            lss.x += v.x * v.x; lss.y += v.y * v.y;
            lss.z += v.z * v.z; lss.w += v.w * v.w;
        }
    }

    // block-level column reduction (reuse Xsm)
    __syncthreads();
    float* ps  = Xsm;          // [8][128]
    float* pss = Xsm + 1024;   // [8][128]
    int o = ox * 4;
    ps[ny * 128 + o + 0] = ls.x;  ps[ny * 128 + o + 1] = ls.y;
    ps[ny * 128 + o + 2] = ls.z;  ps[ny * 128 + o + 3] = ls.w;
    pss[ny * 128 + o + 0] = lss.x; pss[ny * 128 + o + 1] = lss.y;
    pss[ny * 128 + o + 2] = lss.z; pss[ny * 128 + o + 3] = lss.w;
    __syncthreads();
    if (tid < 128) {
        float s = 0.f, ss = 0.f;
#pragma unroll
        for (int q = 0; q < 8; ++q) {
            s  += ps[q * 128 + tid];
            ss += pss[q * 128 + tid];
        }
        atomicAdd(&g_stats[tid], s);
        atomicAdd(&g_stats[128 + tid], ss);
    }
}

// ---------------- kernel 5: finalize BN scale/shift ----------------
__global__ void k_bnfin(const float* __restrict__ gamma,
                        const float* __restrict__ beta,
                        float invN) {
    int c = threadIdx.x;
    float mu  = g_stats[c] * invN;
    float var = fmaxf(g_stats[128 + c] * invN - mu * mu, 0.f);
    float sc  = __ldg(gamma + c) * rsqrtf(var + 1e-5f);
    g_scale[c] = sc;
    g_shift[c] = __ldg(beta + c) - mu * sc;
}

// ---------------- kernel 6: apply BN elementwise ----------------
__global__ void k_apply(float* __restrict__ out, int n4) {
    int i = blockIdx.x * blockDim.x + threadIdx.x;
    if (i >= n4) return;
    int c = i & 31;
    float4 v  = ((float4*)out)[i];
    float4 sc = ((const float4*)g_scale)[c];
    float4 sh = ((const float4*)g_shift)[c];
    v.x = fmaf(v.x, sc.x, sh.x);
    v.y = fmaf(v.y, sc.y, sh.y);
    v.z = fmaf(v.z, sc.z, sh.z);
    v.w = fmaf(v.w, sc.w, sh.w);
    ((float4*)out)[i] = v;
}

// ---------------- launch ----------------
extern "C" void kernel_launch(void* const* d_in, const int* in_sizes, int n_in,
                              void* d_out, int out_size) {
    const float* feat   = (const float*)d_in[0];
    const int*   src    = (const int*)d_in[1];
    const int*   dst    = (const int*)d_in[2];
    const float* ew     = (const float*)d_in[3];
    const float* Wneigh = (const float*)d_in[4];
    const float* Wself  = (const float*)d_in[5];
    const float* b_self = (const float*)d_in[6];
    const float* bias   = (const float*)d_in[7];
    const float* gamma  = (const float*)d_in[8];
    const float* beta   = (const float*)d_in[9];
    float* out = (float*)d_out;

    int N = in_sizes[0] / 128;
    int E = in_sizes[1];

    cudaFuncSetAttribute(k_gemm, cudaFuncAttributeMaxDynamicSharedMemorySize,
                         196608);

    int nn4 = N * 32;                 // neigh float4 count
    int nd4 = (N + 3) / 4;            // deg float4 count
    k_zero<<<(nn4 + 255) / 256, 256>>>(nn4, nd4);
    k_wprep<<<32, 256>>>(Wneigh, Wself);
    k_scatter<<<(E + 7) / 8, 256>>>(feat, src, dst, ew, E);
    k_gemm<<<(N + 63) / 64, 256, 196608>>>(feat, b_self, bias, out, N);
    k_bnfin<<<1, 128>>>(gamma, beta, 1.0f / (float)N);
    k_apply<<<(nn4 + 255) / 256, 256>>>(out, nn4);
}